// round 1
// baseline (speedup 1.0000x reference)
#include <cuda_runtime.h>

// Problem shapes (fixed by setup_inputs)
#define BB 256
#define LL 512
#define DD 64
#define EPS_LOG 1e-7f
#define EPS_COS 1e-8f

// Per-batch partial results (allowed scratch: __device__ global)
__device__ float g_partial[BB];

__global__ __launch_bounds__(512, 2)
void wnl_main(const float* __restrict__ emb,
              const float* __restrict__ probs,
              const float* __restrict__ labels)
{
    const int b    = blockIdx.x;          // batch index, 0..255
    const int tid  = threadIdx.x;         // 0..511
    const int wid  = tid >> 5;            // 0..15
    const int lane = tid & 31;

    __shared__ float s_q[DD];
    __shared__ float s_max[16];
    __shared__ float s_pos[16];
    __shared__ float s_neg[16];

    const float* __restrict__ embB = emb    + (size_t)b * LL * DD;
    const float* __restrict__ labB = labels + (size_t)b * LL;
    const float* __restrict__ prbB = probs  + (size_t)b * LL;

    // ---- load query row q = emb[b][b][:]  (b < LL always since B<=L) ----
    if (tid < DD) s_q[tid] = embB[b * DD + tid];
    __syncthreads();

    // each lane owns 2 query elements (register resident for whole loop)
    float2 q2 = *(const float2*)&s_q[lane * 2];

    // query norm (redundant per warp; 5 shfls, negligible)
    float nq2 = q2.x * q2.x + q2.y * q2.y;
    #pragma unroll
    for (int o = 16; o; o >>= 1) nq2 += __shfl_xor_sync(0xffffffffu, nq2, o);
    const float nq = sqrtf(nq2);

    // ---- masked row-max of relu(cos(q, x_k)) * label_k over k ----
    float m = 0.f;
    const int base = wid * 32;            // warp w handles rows [32w, 32w+32)
    #pragma unroll 4
    for (int i = 0; i < 32; i++) {
        const int k = base + i;
        float2 x2 = *(const float2*)&embB[k * DD + lane * 2]; // coalesced 256B/warp
        float d = q2.x * x2.x + q2.y * x2.y;   // dot partial
        float n = x2.x * x2.x + x2.y * x2.y;   // norm^2 partial
        #pragma unroll
        for (int o = 16; o; o >>= 1) {
            d += __shfl_xor_sync(0xffffffffu, d, o);
            n += __shfl_xor_sync(0xffffffffu, n, o);
        }
        const float lab  = __ldg(&labB[k]);    // warp-uniform broadcast
        const float cosv = d / fmaxf(nq * sqrtf(n), EPS_COS);
        m = fmaxf(m, fmaxf(cosv, 0.f) * lab);  // relu + mask + max
    }

    // ---- per-row log sums (one element per thread; L == blockDim) ----
    const float p  = prbB[tid];
    const float y  = labB[tid];
    const float pe = p + EPS_LOG;
    float pos = y * logf(pe);          // sum -> positive_loss term (before minus)
    float neg = logf(1.0f - pe);       // sum -> log_neg[b]
    #pragma unroll
    for (int o = 16; o; o >>= 1) {
        pos += __shfl_xor_sync(0xffffffffu, pos, o);
        neg += __shfl_xor_sync(0xffffffffu, neg, o);
    }

    if (lane == 0) { s_max[wid] = m; s_pos[wid] = pos; s_neg[wid] = neg; }
    __syncthreads();

    // ---- final block combine on warp 0 ----
    if (wid == 0) {
        float mm = (lane < 16) ? s_max[lane] : 0.f;
        float pp = (lane < 16) ? s_pos[lane] : 0.f;
        float nn = (lane < 16) ? s_neg[lane] : 0.f;
        #pragma unroll
        for (int o = 8; o; o >>= 1) {
            mm = fmaxf(mm, __shfl_xor_sync(0xffffffffu, mm, o));
            pp += __shfl_xor_sync(0xffffffffu, pp, o);
            nn += __shfl_xor_sync(0xffffffffu, nn, o);
        }
        if (lane == 0) {
            const float labdiag = labB[b];                 // labels[b, b]
            const float wnl = (labdiag == 0.f) ? mm : 0.f; // weak-negative weight
            // contribution: -pos_sum  - wnl * log_neg_sum
            g_partial[b] = -pp - wnl * nn;
        }
    }
}

__global__ void wnl_reduce(float* __restrict__ out)
{
    const int tid  = threadIdx.x;     // 256 threads
    const int wid  = tid >> 5;        // 0..7
    const int lane = tid & 31;
    __shared__ float s_sum[8];

    float v = g_partial[tid];
    #pragma unroll
    for (int o = 16; o; o >>= 1) v += __shfl_xor_sync(0xffffffffu, v, o);
    if (lane == 0) s_sum[wid] = v;
    __syncthreads();

    if (wid == 0) {
        float s = (lane < 8) ? s_sum[lane] : 0.f;
        #pragma unroll
        for (int o = 4; o; o >>= 1) s += __shfl_xor_sync(0xffffffffu, s, o);
        if (lane == 0) out[0] = s / (float)BB;
    }
}

extern "C" void kernel_launch(void* const* d_in, const int* in_sizes, int n_in,
                              void* d_out, int out_size)
{
    const float* emb    = (const float*)d_in[0]; // (256, 512, 64) f32
    const float* probs  = (const float*)d_in[1]; // (256, 512) f32
    const float* labels = (const float*)d_in[2]; // (256, 512) f32
    float* out = (float*)d_out;                  // scalar f32

    wnl_main<<<BB, 512>>>(emb, probs, labels);
    wnl_reduce<<<1, 256>>>(out);
}

// round 2
// speedup vs baseline: 1.5258x; 1.5258x over previous
#include <cuda_runtime.h>

#define BB 256
#define LL 512
#define DD 64
#define EPS_LOG 1e-7f
#define EPS_COS 1e-8f

// Per-half-batch partials (512 = 256 batches x 2 halves) + completion counter
__device__ float g_m[2 * BB];
__device__ float g_pos[2 * BB];
__device__ float g_neg[2 * BB];
__device__ int   g_cnt = 0;

__global__ __launch_bounds__(256)
void wnl_fused(const float* __restrict__ emb,
               const float* __restrict__ probs,
               const float* __restrict__ labels,
               float* __restrict__ out)
{
    const int bid  = blockIdx.x;       // 0..511
    const int b    = bid >> 1;         // batch 0..255
    const int h    = bid & 1;          // half 0/1
    const int tid  = threadIdx.x;      // 0..255
    const int wid  = tid >> 5;         // 0..7
    const int lane = tid & 31;
    const int g    = lane >> 3;        // 4 row-groups per warp
    const int s    = lane & 7;         // 8 lanes per row

    __shared__ float s_q[DD];
    __shared__ float s_m[8], s_pos[8], s_neg[8], s_sum[8];
    __shared__ int   s_last;

    const float* __restrict__ embB = emb    + (size_t)b * LL * DD;
    const float* __restrict__ labB = labels + (size_t)b * LL;
    const float* __restrict__ prbB = probs  + (size_t)b * LL;

    // query row q = emb[b][b][:]
    if (tid < DD) s_q[tid] = embB[b * DD + tid];
    if (tid == 0) s_last = 0;
    __syncthreads();

    // lane owns q[s*4..s*4+3] and q[32+s*4..32+s*4+3]
    const float4 qa = *(const float4*)&s_q[s * 4];
    const float4 qb = *(const float4*)&s_q[32 + s * 4];

    // ||q||^2 via 8-lane butterfly (redundant per group, negligible)
    float nq2 = qa.x*qa.x + qa.y*qa.y + qa.z*qa.z + qa.w*qa.w
              + qb.x*qb.x + qb.y*qb.y + qb.z*qb.z + qb.w*qb.w;
    #pragma unroll
    for (int o = 4; o; o >>= 1) nq2 += __shfl_xor_sync(0xffffffffu, nq2, o);
    const float nq = sqrtf(nq2);

    // ---- masked row-max of relu(cos) over this half's 256 rows ----
    float m = 0.f;
    const int rowBase = h * 256 + wid * 32;   // warp covers 32 rows, 4 per iter
    #pragma unroll
    for (int i = 0; i < 8; i++) {
        const int k = rowBase + i * 4 + g;
        const float* rp = embB + (size_t)k * DD;
        // both loads fully coalesced: 4 rows x 1 line per instruction
        const float4 xa = *(const float4*)(rp + s * 4);
        const float4 xb = *(const float4*)(rp + 32 + s * 4);
        float d = qa.x*xa.x + qa.y*xa.y + qa.z*xa.z + qa.w*xa.w
                + qb.x*xb.x + qb.y*xb.y + qb.z*xb.z + qb.w*xb.w;
        float n = xa.x*xa.x + xa.y*xa.y + xa.z*xa.z + xa.w*xa.w
                + xb.x*xb.x + xb.y*xb.y + xb.z*xb.z + xb.w*xb.w;
        #pragma unroll
        for (int o = 4; o; o >>= 1) {
            d += __shfl_xor_sync(0xffffffffu, d, o);
            n += __shfl_xor_sync(0xffffffffu, n, o);
        }
        const float lab  = __ldg(&labB[k]);
        const float cosv = d / fmaxf(nq * sqrtf(n), EPS_COS);
        m = fmaxf(m, fmaxf(cosv, 0.f) * lab);
    }

    // ---- this half's log sums (one l per thread) ----
    const int   l  = h * 256 + tid;
    const float pe = prbB[l] + EPS_LOG;
    float pos = labB[l] * logf(pe);
    float neg = logf(1.0f - pe);

    // warp combine: max(m), sum(pos), sum(neg)
    #pragma unroll
    for (int o = 16; o; o >>= 1) {
        m   = fmaxf(m, __shfl_xor_sync(0xffffffffu, m, o));
        pos += __shfl_xor_sync(0xffffffffu, pos, o);
        neg += __shfl_xor_sync(0xffffffffu, neg, o);
    }
    if (lane == 0) { s_m[wid] = m; s_pos[wid] = pos; s_neg[wid] = neg; }
    __syncthreads();

    if (wid == 0) {
        float mm = (lane < 8) ? s_m[lane]   : 0.f;
        float pp = (lane < 8) ? s_pos[lane] : 0.f;
        float nn = (lane < 8) ? s_neg[lane] : 0.f;
        #pragma unroll
        for (int o = 4; o; o >>= 1) {
            mm = fmaxf(mm, __shfl_xor_sync(0xffffffffu, mm, o));
            pp += __shfl_xor_sync(0xffffffffu, pp, o);
            nn += __shfl_xor_sync(0xffffffffu, nn, o);
        }
        if (lane == 0) {
            g_m[bid] = mm; g_pos[bid] = pp; g_neg[bid] = nn;
            __threadfence();
            const int old = atomicAdd(&g_cnt, 1);
            if (old == 2 * BB - 1) s_last = 1;   // this block finishes the job
        }
    }
    __syncthreads();

    // ---- last-block final combine (deterministic fixed-order sum) ----
    if (s_last) {
        __threadfence();
        const int b2 = tid;                       // 0..255, one batch per thread
        const float mm = fmaxf(__ldcg(&g_m[2*b2]),  __ldcg(&g_m[2*b2+1]));
        const float pp = __ldcg(&g_pos[2*b2]) + __ldcg(&g_pos[2*b2+1]);
        const float nn = __ldcg(&g_neg[2*b2]) + __ldcg(&g_neg[2*b2+1]);
        const float labdiag = __ldg(&labels[(size_t)b2 * LL + b2]);
        const float wnl = (labdiag == 0.f) ? mm : 0.f;
        float contrib = -pp - wnl * nn;

        #pragma unroll
        for (int o = 16; o; o >>= 1)
            contrib += __shfl_xor_sync(0xffffffffu, contrib, o);
        if (lane == 0) s_sum[wid] = contrib;
        __syncthreads();
        if (wid == 0) {
            float t = (lane < 8) ? s_sum[lane] : 0.f;
            #pragma unroll
            for (int o = 4; o; o >>= 1) t += __shfl_xor_sync(0xffffffffu, t, o);
            if (lane == 0) {
                out[0] = t / (float)BB;
                g_cnt = 0;                        // reset for next graph replay
            }
        }
    }
}

extern "C" void kernel_launch(void* const* d_in, const int* in_sizes, int n_in,
                              void* d_out, int out_size)
{
    const float* emb    = (const float*)d_in[0]; // (256, 512, 64) f32
    const float* probs  = (const float*)d_in[1]; // (256, 512) f32
    const float* labels = (const float*)d_in[2]; // (256, 512) f32
    float* out = (float*)d_out;                  // scalar f32

    wnl_fused<<<2 * BB, 256>>>(emb, probs, labels, out);
}